// round 7
// baseline (speedup 1.0000x reference)
#include <cuda_runtime.h>

#define NN 100000
#define NE 1600000
#define NP 200000

// ---------------- scratch (device globals: alloc-guard safe) ----------------
__device__ int   g_is64;                    // 1 if index inputs are int64
__device__ __align__(16) float g_deg[NN];   // 1/deg
__device__ __align__(16) float g_dis[NN];   // 1/sqrt(deg)
__device__ int   g_cnt[NN];                 // in-degree histogram
__device__ int   g_off[NN + 1];             // CSR offsets
__device__ int   g_cur[NN];                 // placement cursors
__device__ int   g_src[NE];
__device__ int   g_dst[NE];
__device__ int   g_csrc[NE];                // CSR: src per in-edge slot
__device__ __align__(16) float g_bufA[NN * 128];
__device__ __align__(16) float g_bufB[NN * 128];
__device__ __align__(16) float g_bufC[NN * 128];

// ---------------- index dtype detection ----------------
__global__ void k_detect(const void* __restrict__ ei) {
    if (threadIdx.x != 0 || blockIdx.x != 0) return;
    const unsigned int* p = (const unsigned int*)ei;
    unsigned int acc = 0;
    #pragma unroll
    for (int i = 0; i < 16; i++) acc |= p[2 * i + 1];  // high words if int64
    g_is64 = (acc == 0u) ? 1 : 0;
}

__device__ __forceinline__ int load_idx(const void* p, int i) {
    if (g_is64) return (int)((const long long*)p)[i];
    return ((const int*)p)[i];
}

// ---------------- prep ----------------
__global__ void k_zero() {
    int i = blockIdx.x * 256 + threadIdx.x;
    if (i < NN) g_cnt[i] = 0;
}

__global__ void k_prep(const void* __restrict__ ei) {
    int e = blockIdx.x * 256 + threadIdx.x;
    if (e >= NE) return;
    int s = load_idx(ei, e);
    int d = load_idx(ei, NE + e);
    g_src[e] = s;
    g_dst[e] = d;
    atomicAdd(&g_cnt[d], 1);
}

__global__ void k_finalize() {
    int i = blockIdx.x * 256 + threadIdx.x;
    if (i >= NN) return;
    float deg = (float)g_cnt[i] + 1.f;
    g_deg[i] = 1.f / deg;
    g_dis[i] = rsqrtf(deg);
}

// single-block exclusive scan of g_cnt -> g_off (and init g_cur)
__global__ __launch_bounds__(1024) void k_scan() {
    __shared__ int chunk[1024];
    const int C = (NN + 1023) / 1024;   // 98
    int t = threadIdx.x;
    int base = t * C;
    int s = 0;
    for (int i = 0; i < C; i++) {
        int idx = base + i;
        if (idx < NN) s += g_cnt[idx];
    }
    chunk[t] = s;
    __syncthreads();
    for (int o = 1; o < 1024; o <<= 1) {
        int v = (t >= o) ? chunk[t - o] : 0;
        __syncthreads();
        chunk[t] += v;
        __syncthreads();
    }
    int pre = (t == 0) ? 0 : chunk[t - 1];
    for (int i = 0; i < C; i++) {
        int idx = base + i;
        if (idx < NN) {
            g_off[idx] = pre;
            g_cur[idx] = pre;
            pre += g_cnt[idx];
        }
    }
    if (t == 1023) g_off[NN] = pre;
}

__global__ void k_place() {
    int e = blockIdx.x * 256 + threadIdx.x;
    if (e >= NE) return;
    int d = g_dst[e];
    int p = atomicAdd(&g_cur[d], 1);
    g_csrc[p] = g_src[e];
}

// ---------------- GEMM: h = act(X)@W ; Hs = h*dis ; AGG = h*deg_inv + b ----
// CIN=128 fixed. Tile: 64 rows x COUT cols, 256 threads.
template <int COUT, bool RELU>
__global__ __launch_bounds__(256) void k_gemm(
    const float* __restrict__ X, const float* __restrict__ W,
    const float* __restrict__ bias,
    float* __restrict__ Hs, float* __restrict__ AGG)
{
    extern __shared__ float sm[];
    float* Ws = sm;                   // [128 * COUT]
    float* Xs = sm + 128 * COUT;      // [64 * 129]
    const int tid = threadIdx.x;
    const int row_base = blockIdx.x * 64;

    {
        const float4* src4 = (const float4*)W;
        float4* dst4 = (float4*)Ws;
        #pragma unroll
        for (int i = tid; i < 128 * COUT / 4; i += 256) dst4[i] = src4[i];
    }
    #pragma unroll
    for (int i = tid; i < 64 * 32; i += 256) {
        int r  = i >> 5;
        int kk = i & 31;
        float4 v = make_float4(0.f, 0.f, 0.f, 0.f);
        int gr = row_base + r;
        if (gr < NN) v = ((const float4*)X)[gr * 32 + kk];
        if (RELU) {
            v.x = fmaxf(v.x, 0.f); v.y = fmaxf(v.y, 0.f);
            v.z = fmaxf(v.z, 0.f); v.w = fmaxf(v.w, 0.f);
        }
        float* xr = Xs + r * 129 + kk * 4;
        xr[0] = v.x; xr[1] = v.y; xr[2] = v.z; xr[3] = v.w;
    }
    __syncthreads();

    const int tc = tid & 15;
    const int tr = tid >> 4;
    const int r0 = tr * 4;
    constexpr int NB = COUT / 64;

    float4 acc[4][NB];
    #pragma unroll
    for (int i = 0; i < 4; i++)
        #pragma unroll
        for (int b = 0; b < NB; b++) acc[i][b] = make_float4(0.f, 0.f, 0.f, 0.f);

    const float4* Ws4 = (const float4*)Ws;
    #pragma unroll 8
    for (int k = 0; k < 128; k++) {
        float4 w[NB];
        #pragma unroll
        for (int b = 0; b < NB; b++) w[b] = Ws4[k * (COUT / 4) + b * 16 + tc];
        #pragma unroll
        for (int i = 0; i < 4; i++) {
            float xv = Xs[(r0 + i) * 129 + k];
            #pragma unroll
            for (int b = 0; b < NB; b++) {
                acc[i][b].x += xv * w[b].x;
                acc[i][b].y += xv * w[b].y;
                acc[i][b].z += xv * w[b].z;
                acc[i][b].w += xv * w[b].w;
            }
        }
    }

    float4 bv[NB];
    #pragma unroll
    for (int b = 0; b < NB; b++) bv[b] = ((const float4*)bias)[b * 16 + tc];
    #pragma unroll
    for (int i = 0; i < 4; i++) {
        int r = row_base + r0 + i;
        if (r >= NN) break;
        float di = g_deg[r];
        float ds = g_dis[r];
        #pragma unroll
        for (int b = 0; b < NB; b++) {
            float4 h = acc[i][b];
            float4 hs;
            hs.x = h.x * ds; hs.y = h.y * ds; hs.z = h.z * ds; hs.w = h.w * ds;
            ((float4*)Hs)[r * (COUT / 4) + b * 16 + tc] = hs;
            float4 a;
            a.x = h.x * di + bv[b].x;
            a.y = h.y * di + bv[b].y;
            a.z = h.z * di + bv[b].z;
            a.w = h.w * di + bv[b].w;
            ((float4*)AGG)[r * (COUT / 4) + b * 16 + tc] = a;
        }
    }
}

// ---------------- gather aggregation: AGG[d] += dis[d] * sum Hs[src] -------
template <int COUT>
__global__ __launch_bounds__(256) void k_agg(const float* __restrict__ Hs,
                                             float* __restrict__ AGG)
{
    constexpr int LPN = COUT / 4;        // float4 lanes per node (32 or 16)
    constexpr int NPB = 256 / LPN;       // nodes per block (8 or 16)
    int n = blockIdx.x * NPB + threadIdx.x / LPN;
    int lane = threadIdx.x % LPN;
    if (n >= NN) return;

    int beg = g_off[n];
    int end = g_off[n + 1];
    float4 acc = make_float4(0.f, 0.f, 0.f, 0.f);

    int e = beg;
    for (; e + 3 < end; e += 4) {
        int s0 = g_csrc[e];
        int s1 = g_csrc[e + 1];
        int s2 = g_csrc[e + 2];
        int s3 = g_csrc[e + 3];
        float4 v0 = ((const float4*)Hs)[s0 * LPN + lane];
        float4 v1 = ((const float4*)Hs)[s1 * LPN + lane];
        float4 v2 = ((const float4*)Hs)[s2 * LPN + lane];
        float4 v3 = ((const float4*)Hs)[s3 * LPN + lane];
        acc.x += v0.x + v1.x + v2.x + v3.x;
        acc.y += v0.y + v1.y + v2.y + v3.y;
        acc.z += v0.z + v1.z + v2.z + v3.z;
        acc.w += v0.w + v1.w + v2.w + v3.w;
    }
    for (; e < end; e++) {
        int s = g_csrc[e];
        float4 v = ((const float4*)Hs)[s * LPN + lane];
        acc.x += v.x; acc.y += v.y; acc.z += v.z; acc.w += v.w;
    }

    float ds = g_dis[n];
    float4* outp = (float4*)AGG + n * LPN + lane;
    float4 o = *outp;
    o.x += ds * acc.x;
    o.y += ds * acc.y;
    o.z += ds * acc.z;
    o.w += ds * acc.w;
    *outp = o;
}

// ---------------- pair dot decode (COUT=64, warp per pair) ----------------
__global__ __launch_bounds__(256) void k_pairs(
    const float* __restrict__ H,
    const void* __restrict__ ni, const void* __restrict__ nj,
    float* __restrict__ out)
{
    int t = blockIdx.x * 256 + threadIdx.x;
    int p = t >> 5;
    int lane = t & 31;
    if (p >= NP) return;
    int i = load_idx(ni, p);
    int j = load_idx(nj, p);
    float2 a = ((const float2*)H)[i * 32 + lane];
    float2 b = ((const float2*)H)[j * 32 + lane];
    float s = a.x * b.x + a.y * b.y;
    #pragma unroll
    for (int o = 16; o; o >>= 1) s += __shfl_xor_sync(0xFFFFFFFFu, s, o);
    if (lane == 0) out[p] = s;
}

// ---------------- launch ----------------
extern "C" void kernel_launch(void* const* d_in, const int* in_sizes, int n_in,
                              void* d_out, int out_size)
{
    const float* x  = (const float*)d_in[0];
    const void*  ei = d_in[1];
    const void*  ni = d_in[2];
    const void*  nj = d_in[3];
    const float* W1 = (const float*)d_in[4];
    const float* b1 = (const float*)d_in[5];
    const float* W2 = (const float*)d_in[6];
    const float* b2 = (const float*)d_in[7];
    const float* W3 = (const float*)d_in[8];
    const float* b3 = (const float*)d_in[9];
    float* out = (float*)d_out;

    float *bufA, *bufB, *bufC;
    cudaGetSymbolAddress((void**)&bufA, g_bufA);
    cudaGetSymbolAddress((void**)&bufB, g_bufB);
    cudaGetSymbolAddress((void**)&bufC, g_bufC);

    const int smem128 = (128 * 128 + 64 * 129) * 4;   // 98560 B
    const int smem64  = (128 * 64  + 64 * 129) * 4;   // 65792 B
    cudaFuncSetAttribute(k_gemm<128, false>, cudaFuncAttributeMaxDynamicSharedMemorySize, smem128);
    cudaFuncSetAttribute(k_gemm<128, true>,  cudaFuncAttributeMaxDynamicSharedMemorySize, smem128);
    cudaFuncSetAttribute(k_gemm<64,  true>,  cudaFuncAttributeMaxDynamicSharedMemorySize, smem64);

    // dtype detection, then prep: degrees + CSR by dst
    k_detect<<<1, 32>>>(ei);
    k_zero<<<(NN + 255) / 256, 256>>>();
    k_prep<<<(NE + 255) / 256, 256>>>(ei);
    k_finalize<<<(NN + 255) / 256, 256>>>();
    k_scan<<<1, 1024>>>();
    k_place<<<(NE + 255) / 256, 256>>>();

    const int gb = (NN + 63) / 64;   // 1563 blocks

    // layer 1
    k_gemm<128, false><<<gb, 256, smem128>>>(x, W1, b1, bufA, bufB);
    k_agg<128><<<(NN + 7) / 8, 256>>>(bufA, bufB);
    // layer 2
    k_gemm<128, true><<<gb, 256, smem128>>>(bufB, W2, b2, bufA, bufC);
    k_agg<128><<<(NN + 7) / 8, 256>>>(bufA, bufC);
    // layer 3 (COUT=64)
    k_gemm<64, true><<<gb, 256, smem64>>>(bufC, W3, b3, bufA, bufB);
    k_agg<64><<<(NN + 15) / 16, 256>>>(bufA, bufB);

    // link decode
    k_pairs<<<(NP * 32) / 256, 256>>>(bufB, ni, nj, out);
}

// round 12
// speedup vs baseline: 1.1977x; 1.1977x over previous
#include <cuda_runtime.h>
#include <cuda_bf16.h>

#define NN 100000
#define NE 1600000
#define NP 200000

// ================= scratch (device globals) =================
__device__ int   g_is64;
__device__ __align__(16) float g_deg[NN];   // 1/deg
__device__ __align__(16) float g_dis[NN];   // 1/sqrt(deg)
__device__ int   g_cnt[NN];
__device__ int   g_off[NN + 1];
__device__ int   g_cur[NN];
__device__ int   g_src[NE];
__device__ int   g_dst[NE];
__device__ int   g_csrc[NE];
__device__ __align__(16) float g_bufA[NN * 128];
__device__ __align__(16) float g_bufB[NN * 128];
__device__ __align__(16) float g_bufC[NN * 128];
// W^T split: bf16 [n][k] row-major, k-stride 128
__device__ __align__(16) __nv_bfloat16 g_Wh[128 * 128];
__device__ __align__(16) __nv_bfloat16 g_Wl[128 * 128];

// ================= helpers =================
__device__ __forceinline__ unsigned smem_u32(const void* p) {
    unsigned a;
    asm("{ .reg .u64 t; cvta.to.shared.u64 t, %1; cvt.u32.u64 %0, t; }"
        : "=r"(a) : "l"(p));
    return a;
}

__device__ __forceinline__ void ldsm4(unsigned* r, unsigned addr) {
    asm volatile("ldmatrix.sync.aligned.m8n8.x4.shared.b16 {%0,%1,%2,%3}, [%4];"
                 : "=r"(r[0]), "=r"(r[1]), "=r"(r[2]), "=r"(r[3]) : "r"(addr));
}

__device__ __forceinline__ void mma16816(float* d, const unsigned* a, const unsigned* b) {
    asm volatile("mma.sync.aligned.m16n8k16.row.col.f32.bf16.bf16.f32 "
                 "{%0,%1,%2,%3}, {%4,%5,%6,%7}, {%8,%9}, {%0,%1,%2,%3};"
                 : "+f"(d[0]), "+f"(d[1]), "+f"(d[2]), "+f"(d[3])
                 : "r"(a[0]), "r"(a[1]), "r"(a[2]), "r"(a[3]), "r"(b[0]), "r"(b[1]));
}

__device__ __forceinline__ unsigned pack2(float a, float b) {
    __nv_bfloat162 t(__float2bfloat16_rn(a), __float2bfloat16_rn(b));
    return *reinterpret_cast<unsigned*>(&t);
}
__device__ __forceinline__ unsigned pack_hi(float a, float b, float& ra, float& rb) {
    __nv_bfloat16 ha = __float2bfloat16_rn(a), hb = __float2bfloat16_rn(b);
    ra = a - __bfloat162float(ha);
    rb = b - __bfloat162float(hb);
    __nv_bfloat162 t(ha, hb);
    return *reinterpret_cast<unsigned*>(&t);
}

// ================= index dtype detect / prep =================
__global__ void k_detect(const void* __restrict__ ei) {
    if (threadIdx.x != 0 || blockIdx.x != 0) return;
    const unsigned* p = (const unsigned*)ei;
    unsigned acc = 0;
    #pragma unroll
    for (int i = 0; i < 16; i++) acc |= p[2 * i + 1];
    g_is64 = (acc == 0u) ? 1 : 0;
}

__device__ __forceinline__ int load_idx(const void* p, int i) {
    if (g_is64) return (int)((const long long*)p)[i];
    return ((const int*)p)[i];
}

__global__ void k_zero() {
    int i = blockIdx.x * 256 + threadIdx.x;
    if (i < NN) g_cnt[i] = 0;
}

__global__ void k_prep(const void* __restrict__ ei) {
    int e = blockIdx.x * 256 + threadIdx.x;
    if (e >= NE) return;
    int s = load_idx(ei, e);
    int d = load_idx(ei, NE + e);
    g_src[e] = s;
    g_dst[e] = d;
    atomicAdd(&g_cnt[d], 1);
}

__global__ void k_finalize() {
    int i = blockIdx.x * 256 + threadIdx.x;
    if (i >= NN) return;
    float deg = (float)g_cnt[i] + 1.f;
    g_deg[i] = 1.f / deg;
    g_dis[i] = rsqrtf(deg);
}

__global__ __launch_bounds__(1024) void k_scan() {
    __shared__ int chunk[1024];
    const int C = (NN + 1023) / 1024;
    int t = threadIdx.x;
    int base = t * C;
    int s = 0;
    for (int i = 0; i < C; i++) {
        int idx = base + i;
        if (idx < NN) s += g_cnt[idx];
    }
    chunk[t] = s;
    __syncthreads();
    for (int o = 1; o < 1024; o <<= 1) {
        int v = (t >= o) ? chunk[t - o] : 0;
        __syncthreads();
        chunk[t] += v;
        __syncthreads();
    }
    int pre = (t == 0) ? 0 : chunk[t - 1];
    for (int i = 0; i < C; i++) {
        int idx = base + i;
        if (idx < NN) {
            g_off[idx] = pre;
            g_cur[idx] = pre;
            pre += g_cnt[idx];
        }
    }
    if (t == 1023) g_off[NN] = pre;
}

__global__ void k_place() {
    int e = blockIdx.x * 256 + threadIdx.x;
    if (e >= NE) return;
    int d = g_dst[e];
    int p = atomicAdd(&g_cur[d], 1);
    g_csrc[p] = g_src[e];
}

// ================= W prep: transpose + bf16 split (once/layer) ========
template <int COUT>
__global__ void k_convW(const float* __restrict__ W) {
    int t = blockIdx.x * 256 + threadIdx.x;
    if (t >= COUT * 32) return;
    int n = t >> 5;
    int k0 = (t & 31) * 4;
    float w0 = W[(k0 + 0) * COUT + n];
    float w1 = W[(k0 + 1) * COUT + n];
    float w2 = W[(k0 + 2) * COUT + n];
    float w3 = W[(k0 + 3) * COUT + n];
    float r0, r1, r2, r3;
    unsigned h01 = pack_hi(w0, w1, r0, r1);
    unsigned h23 = pack_hi(w2, w3, r2, r3);
    unsigned l01 = pack2(r0, r1);
    unsigned l23 = pack2(r2, r3);
    *(uint2*)((char*)g_Wh + (n * 128 + k0) * 2) = make_uint2(h01, h23);
    *(uint2*)((char*)g_Wl + (n * 128 + k0) * 2) = make_uint2(l01, l23);
}

// ================= mma.sync GEMM =================
// h = act(X) @ W ; Hs = h*dis ; AGG = h/deg + b
// CTA: 256 thr (8 warps), tile 64 rows x COUT. Warp grid 4x2, warp tile 16 x COUT/2.
// 3-term bf16 split: XhWh + XhWl + XlWh, fp32 accum.
#define SA 136   // smem k-stride in elems (272B: ldmatrix conflict-free)

template <int COUT, bool RELU>
__global__ __launch_bounds__(256, 2) void k_mma_gemm(
    const float* __restrict__ X, const float* __restrict__ bias,
    float* __restrict__ Hs, float* __restrict__ AGG)
{
    extern __shared__ char sm[];
    constexpr int ASZ = 64 * SA * 2;         // bytes per A split matrix (17408)
    constexpr int BSZ = COUT * SA * 2;       // bytes per B split matrix
    char* sAh = sm;
    char* sAl = sm + ASZ;
    char* sBh = sm + 2 * ASZ;
    char* sBl = sm + 2 * ASZ + BSZ;
    const unsigned uAh = smem_u32(sAh), uAl = smem_u32(sAl);
    const unsigned uBh = smem_u32(sBh), uBl = smem_u32(sBl);

    const int tid = threadIdx.x;
    const int wid = tid >> 5;
    const int lane = tid & 31;
    const int base = blockIdx.x * 64;
    constexpr int NT = COUT / 16;            // n8-tiles per warp (8 or 4)

    // ---- A: load fp32 X tile, (ReLU), split bf16 hi/lo ----
    {
        const float4* X4 = (const float4*)X;
        #pragma unroll
        for (int i = tid; i < 64 * 32; i += 256) {
            int r = i >> 5;
            int k0 = (i & 31) * 4;
            int gr = base + r;
            float4 v = make_float4(0.f, 0.f, 0.f, 0.f);
            if (gr < NN) v = X4[gr * 32 + (k0 >> 2)];
            if (RELU) {
                v.x = fmaxf(v.x, 0.f); v.y = fmaxf(v.y, 0.f);
                v.z = fmaxf(v.z, 0.f); v.w = fmaxf(v.w, 0.f);
            }
            float rx, ry, rz, rw;
            unsigned h01 = pack_hi(v.x, v.y, rx, ry);
            unsigned h23 = pack_hi(v.z, v.w, rz, rw);
            unsigned off = (unsigned)(r * SA + k0) * 2;
            *(uint2*)(sAh + off) = make_uint2(h01, h23);
            *(uint2*)(sAl + off) = make_uint2(pack2(rx, ry), pack2(rz, rw));
        }
    }
    // ---- B: copy W^T splits (bf16 [n][128]) into padded smem ----
    {
        #pragma unroll
        for (int i = tid; i < COUT * 32; i += 256) {
            int n = i >> 5;
            int k0 = (i & 31) * 4;
            unsigned soff = (unsigned)(n * SA + k0) * 2;
            unsigned goff = (unsigned)(n * 128 + k0) * 2;
            *(uint2*)(sBh + soff) = *(const uint2*)((const char*)g_Wh + goff);
            *(uint2*)(sBl + soff) = *(const uint2*)((const char*)g_Wl + goff);
        }
    }
    __syncthreads();

    const int wr = wid & 3;
    const int wc = wid >> 2;
    const int m0 = wr * 16;
    const int n0 = wc * (COUT / 2);

    float acc[NT][4];
    #pragma unroll
    for (int j = 0; j < NT; j++)
        #pragma unroll
        for (int q = 0; q < 4; q++) acc[j][q] = 0.f;

    // intra-warp ldmatrix lane offsets
    const unsigned aoff = (unsigned)((m0 + (lane & 15)) * SA + (lane >> 4) * 8) * 2;
    const int bmat = lane >> 3;              // 0..3
    const int brow = lane & 7;
    const unsigned boff_row = (unsigned)((n0 + (bmat >> 1) * 8 + brow) * SA + (bmat & 1) * 8) * 2;

    #pragma unroll
    for (int ks = 0; ks < 8; ks++) {
        const unsigned k2 = (unsigned)(ks * 16) * 2;
        unsigned ah[4], al[4];
        ldsm4(ah, uAh + aoff + k2);
        ldsm4(al, uAl + aoff + k2);

        unsigned bh[NT][2], bl[NT][2];
        #pragma unroll
        for (int jj = 0; jj < NT / 2; jj++) {
            unsigned bo = boff_row + (unsigned)(jj * 16 * SA) * 2 + k2;
            unsigned t4[4];
            ldsm4(t4, uBh + bo);
            bh[jj * 2][0] = t4[0]; bh[jj * 2][1] = t4[1];
            bh[jj * 2 + 1][0] = t4[2]; bh[jj * 2 + 1][1] = t4[3];
            ldsm4(t4, uBl + bo);
            bl[jj * 2][0] = t4[0]; bl[jj * 2][1] = t4[1];
            bl[jj * 2 + 1][0] = t4[2]; bl[jj * 2 + 1][1] = t4[3];
        }
        #pragma unroll
        for (int j = 0; j < NT; j++) {
            mma16816(acc[j], ah, bh[j]);
            mma16816(acc[j], ah, bl[j]);
            mma16816(acc[j], al, bh[j]);
        }
    }

    // ---- epilogue: fused Hs = h*dis ; AGG = h/deg + b ----
    {
        const int r1 = m0 + (lane >> 2);
        const int r2 = r1 + 8;
        const int gr1 = base + r1;
        const int gr2 = base + r2;
        float ds1 = 0.f, di1 = 0.f, ds2 = 0.f, di2 = 0.f;
        if (gr1 < NN) { ds1 = g_dis[gr1]; di1 = g_deg[gr1]; }
        if (gr2 < NN) { ds2 = g_dis[gr2]; di2 = g_deg[gr2]; }
        #pragma unroll
        for (int j = 0; j < NT; j++) {
            const int col = n0 + j * 8 + (lane & 3) * 2;
            const float2 bv = *(const float2*)(bias + col);
            if (gr1 < NN) {
                float2 hs = make_float2(acc[j][0] * ds1, acc[j][1] * ds1);
                float2 ag = make_float2(acc[j][0] * di1 + bv.x, acc[j][1] * di1 + bv.y);
                *(float2*)(Hs + gr1 * COUT + col) = hs;
                *(float2*)(AGG + gr1 * COUT + col) = ag;
            }
            if (gr2 < NN) {
                float2 hs = make_float2(acc[j][2] * ds2, acc[j][3] * ds2);
                float2 ag = make_float2(acc[j][2] * di2 + bv.x, acc[j][3] * di2 + bv.y);
                *(float2*)(Hs + gr2 * COUT + col) = hs;
                *(float2*)(AGG + gr2 * COUT + col) = ag;
            }
        }
    }
}

// ================= gather aggregation: AGG[d] += dis[d]*sum Hs[src] =======
template <int COUT>
__global__ __launch_bounds__(256) void k_agg(const float* __restrict__ Hs,
                                             float* __restrict__ AGG)
{
    constexpr int LPN = COUT / 4;
    constexpr int NPB = 256 / LPN;
    int n = blockIdx.x * NPB + threadIdx.x / LPN;
    int lane = threadIdx.x % LPN;
    if (n >= NN) return;

    int beg = g_off[n];
    int end = g_off[n + 1];
    float4 acc = make_float4(0.f, 0.f, 0.f, 0.f);

    int e = beg;
    for (; e + 3 < end; e += 4) {
        int s0 = g_csrc[e];
        int s1 = g_csrc[e + 1];
        int s2 = g_csrc[e + 2];
        int s3 = g_csrc[e + 3];
        float4 v0 = ((const float4*)Hs)[s0 * LPN + lane];
        float4 v1 = ((const float4*)Hs)[s1 * LPN + lane];
        float4 v2 = ((const float4*)Hs)[s2 * LPN + lane];
        float4 v3 = ((const float4*)Hs)[s3 * LPN + lane];
        acc.x += v0.x + v1.x + v2.x + v3.x;
        acc.y += v0.y + v1.y + v2.y + v3.y;
        acc.z += v0.z + v1.z + v2.z + v3.z;
        acc.w += v0.w + v1.w + v2.w + v3.w;
    }
    for (; e < end; e++) {
        int s = g_csrc[e];
        float4 v = ((const float4*)Hs)[s * LPN + lane];
        acc.x += v.x; acc.y += v.y; acc.z += v.z; acc.w += v.w;
    }

    float ds = g_dis[n];
    float4* outp = (float4*)AGG + n * LPN + lane;
    float4 o = *outp;
    o.x += ds * acc.x;
    o.y += ds * acc.y;
    o.z += ds * acc.z;
    o.w += ds * acc.w;
    *outp = o;
}

// ================= pair dot decode =================
__global__ __launch_bounds__(256) void k_pairs(
    const float* __restrict__ H,
    const void* __restrict__ ni, const void* __restrict__ nj,
    float* __restrict__ out)
{
    int t = blockIdx.x * 256 + threadIdx.x;
    int p = t >> 5;
    int lane = t & 31;
    if (p >= NP) return;
    int i = load_idx(ni, p);
    int j = load_idx(nj, p);
    float2 a = ((const float2*)H)[i * 32 + lane];
    float2 b = ((const float2*)H)[j * 32 + lane];
    float s = a.x * b.x + a.y * b.y;
    #pragma unroll
    for (int o = 16; o; o >>= 1) s += __shfl_xor_sync(0xFFFFFFFFu, s, o);
    if (lane == 0) out[p] = s;
}

// ================= launch =================
extern "C" void kernel_launch(void* const* d_in, const int* in_sizes, int n_in,
                              void* d_out, int out_size)
{
    const float* x  = (const float*)d_in[0];
    const void*  ei = d_in[1];
    const void*  ni = d_in[2];
    const void*  nj = d_in[3];
    const float* W1 = (const float*)d_in[4];
    const float* b1 = (const float*)d_in[5];
    const float* W2 = (const float*)d_in[6];
    const float* b2 = (const float*)d_in[7];
    const float* W3 = (const float*)d_in[8];
    const float* b3 = (const float*)d_in[9];
    float* out = (float*)d_out;

    float *bufA, *bufB, *bufC;
    cudaGetSymbolAddress((void**)&bufA, g_bufA);
    cudaGetSymbolAddress((void**)&bufB, g_bufB);
    cudaGetSymbolAddress((void**)&bufC, g_bufC);

    const int smem128 = 2 * (64 * SA * 2) + 2 * (128 * SA * 2);  // 104448
    const int smem64  = 2 * (64 * SA * 2) + 2 * (64 * SA * 2);   //  69632
    cudaFuncSetAttribute(k_mma_gemm<128, false>, cudaFuncAttributeMaxDynamicSharedMemorySize, smem128);
    cudaFuncSetAttribute(k_mma_gemm<128, true>,  cudaFuncAttributeMaxDynamicSharedMemorySize, smem128);
    cudaFuncSetAttribute(k_mma_gemm<64,  true>,  cudaFuncAttributeMaxDynamicSharedMemorySize, smem64);

    // dtype detection + degree/CSR prep
    k_detect<<<1, 32>>>(ei);
    k_zero<<<(NN + 255) / 256, 256>>>();
    k_prep<<<(NE + 255) / 256, 256>>>(ei);
    k_finalize<<<(NN + 255) / 256, 256>>>();
    k_scan<<<1, 1024>>>();
    k_place<<<(NE + 255) / 256, 256>>>();

    const int gt = (NN + 63) / 64;   // 1563 tiles

    // layer 1
    k_convW<128><<<(128 * 32) / 256, 256>>>(W1);
    k_mma_gemm<128, false><<<gt, 256, smem128>>>(x, b1, bufA, bufB);
    k_agg<128><<<(NN + 7) / 8, 256>>>(bufA, bufB);
    // layer 2
    k_convW<128><<<(128 * 32) / 256, 256>>>(W2);
    k_mma_gemm<128, true><<<gt, 256, smem128>>>(bufB, b2, bufA, bufC);
    k_agg<128><<<(NN + 7) / 8, 256>>>(bufA, bufC);
    // layer 3 (COUT=64)
    k_convW<64><<<(64 * 32) / 256, 256>>>(W3);
    k_mma_gemm<64, true><<<gt, 256, smem64>>>(bufC, b3, bufA, bufB);
    k_agg<64><<<(NN + 15) / 16, 256>>>(bufA, bufB);

    // link decode
    k_pairs<<<(NP * 32) / 256, 256>>>(bufB, ni, nj, out);
}

// round 13
// speedup vs baseline: 1.2927x; 1.0793x over previous
#include <cuda_runtime.h>
#include <cuda_bf16.h>
#include <cuda_fp16.h>

#define NN 100000
#define NE 1600000
#define NP 200000

// ================= scratch (device globals) =================
__device__ int   g_is64;
__device__ __align__(16) float g_deg[NN];   // 1/deg
__device__ __align__(16) float g_dis[NN];   // 1/sqrt(deg)
__device__ int   g_cnt[NN];
__device__ int   g_off[NN + 1];
__device__ int   g_cur[NN];
__device__ int   g_src[NE];
__device__ int   g_dst[NE];
__device__ int   g_csrc[NE];
__device__ __align__(16) __half g_msg[NN * 128];   // fp16 messages Hs
__device__ __align__(16) float g_bufB[NN * 128];
__device__ __align__(16) float g_bufC[NN * 128];
// W^T split: bf16 [n][k] row-major, k-stride 128
__device__ __align__(16) __nv_bfloat16 g_Wh[128 * 128];
__device__ __align__(16) __nv_bfloat16 g_Wl[128 * 128];

// ================= helpers =================
__device__ __forceinline__ unsigned smem_u32(const void* p) {
    unsigned a;
    asm("{ .reg .u64 t; cvta.to.shared.u64 t, %1; cvt.u32.u64 %0, t; }"
        : "=r"(a) : "l"(p));
    return a;
}

__device__ __forceinline__ void ldsm4(unsigned* r, unsigned addr) {
    asm volatile("ldmatrix.sync.aligned.m8n8.x4.shared.b16 {%0,%1,%2,%3}, [%4];"
                 : "=r"(r[0]), "=r"(r[1]), "=r"(r[2]), "=r"(r[3]) : "r"(addr));
}

__device__ __forceinline__ void mma16816(float* d, const unsigned* a, const unsigned* b) {
    asm volatile("mma.sync.aligned.m16n8k16.row.col.f32.bf16.bf16.f32 "
                 "{%0,%1,%2,%3}, {%4,%5,%6,%7}, {%8,%9}, {%0,%1,%2,%3};"
                 : "+f"(d[0]), "+f"(d[1]), "+f"(d[2]), "+f"(d[3])
                 : "r"(a[0]), "r"(a[1]), "r"(a[2]), "r"(a[3]), "r"(b[0]), "r"(b[1]));
}

__device__ __forceinline__ unsigned pack2(float a, float b) {
    __nv_bfloat162 t(__float2bfloat16_rn(a), __float2bfloat16_rn(b));
    return *reinterpret_cast<unsigned*>(&t);
}
__device__ __forceinline__ unsigned pack_hi(float a, float b, float& ra, float& rb) {
    __nv_bfloat16 ha = __float2bfloat16_rn(a), hb = __float2bfloat16_rn(b);
    ra = a - __bfloat162float(ha);
    rb = b - __bfloat162float(hb);
    __nv_bfloat162 t(ha, hb);
    return *reinterpret_cast<unsigned*>(&t);
}

// ================= index dtype detect / prep =================
__global__ void k_detect(const void* __restrict__ ei) {
    if (threadIdx.x != 0 || blockIdx.x != 0) return;
    const unsigned* p = (const unsigned*)ei;
    unsigned acc = 0;
    #pragma unroll
    for (int i = 0; i < 16; i++) acc |= p[2 * i + 1];
    g_is64 = (acc == 0u) ? 1 : 0;
}

__device__ __forceinline__ int load_idx(const void* p, int i) {
    if (g_is64) return (int)((const long long*)p)[i];
    return ((const int*)p)[i];
}

__global__ void k_zero() {
    int i = blockIdx.x * 256 + threadIdx.x;
    if (i < NN) g_cnt[i] = 0;
}

__global__ void k_prep(const void* __restrict__ ei) {
    int e = blockIdx.x * 256 + threadIdx.x;
    if (e >= NE) return;
    int s = load_idx(ei, e);
    int d = load_idx(ei, NE + e);
    g_src[e] = s;
    g_dst[e] = d;
    atomicAdd(&g_cnt[d], 1);
}

__global__ void k_finalize() {
    int i = blockIdx.x * 256 + threadIdx.x;
    if (i >= NN) return;
    float deg = (float)g_cnt[i] + 1.f;
    g_deg[i] = 1.f / deg;
    g_dis[i] = rsqrtf(deg);
}

__global__ __launch_bounds__(1024) void k_scan() {
    __shared__ int chunk[1024];
    const int C = (NN + 1023) / 1024;
    int t = threadIdx.x;
    int base = t * C;
    int s = 0;
    for (int i = 0; i < C; i++) {
        int idx = base + i;
        if (idx < NN) s += g_cnt[idx];
    }
    chunk[t] = s;
    __syncthreads();
    for (int o = 1; o < 1024; o <<= 1) {
        int v = (t >= o) ? chunk[t - o] : 0;
        __syncthreads();
        chunk[t] += v;
        __syncthreads();
    }
    int pre = (t == 0) ? 0 : chunk[t - 1];
    for (int i = 0; i < C; i++) {
        int idx = base + i;
        if (idx < NN) {
            g_off[idx] = pre;
            g_cur[idx] = pre;
            pre += g_cnt[idx];
        }
    }
    if (t == 1023) g_off[NN] = pre;
}

__global__ void k_place() {
    int e = blockIdx.x * 256 + threadIdx.x;
    if (e >= NE) return;
    int d = g_dst[e];
    int p = atomicAdd(&g_cur[d], 1);
    g_csrc[p] = g_src[e];
}

// ================= W prep: transpose + bf16 split (once/layer) ========
template <int COUT>
__global__ void k_convW(const float* __restrict__ W) {
    int t = blockIdx.x * 256 + threadIdx.x;
    if (t >= COUT * 32) return;
    int n = t >> 5;
    int k0 = (t & 31) * 4;
    float w0 = W[(k0 + 0) * COUT + n];
    float w1 = W[(k0 + 1) * COUT + n];
    float w2 = W[(k0 + 2) * COUT + n];
    float w3 = W[(k0 + 3) * COUT + n];
    float r0, r1, r2, r3;
    unsigned h01 = pack_hi(w0, w1, r0, r1);
    unsigned h23 = pack_hi(w2, w3, r2, r3);
    unsigned l01 = pack2(r0, r1);
    unsigned l23 = pack2(r2, r3);
    *(uint2*)((char*)g_Wh + (n * 128 + k0) * 2) = make_uint2(h01, h23);
    *(uint2*)((char*)g_Wl + (n * 128 + k0) * 2) = make_uint2(l01, l23);
}

// ================= mma.sync GEMM =================
// h = act(X) @ W ; msg = fp16(h*dis) ; AGG = h/deg + b
// CTA: 256 thr (8 warps), tile 64 rows x COUT. Warp grid 4x2, warp tile 16 x COUT/2.
// 3-term bf16 split: XhWh + XhWl + XlWh, fp32 accum.
#define SA 136   // smem k-stride in elems (272B: ldmatrix conflict-free)

template <int COUT, bool RELU>
__global__ __launch_bounds__(256, 2) void k_mma_gemm(
    const float* __restrict__ X, const float* __restrict__ bias,
    __half* __restrict__ Hs, float* __restrict__ AGG)
{
    extern __shared__ char sm[];
    constexpr int ASZ = 64 * SA * 2;         // bytes per A split matrix (17408)
    constexpr int BSZ = COUT * SA * 2;       // bytes per B split matrix
    char* sAh = sm;
    char* sAl = sm + ASZ;
    char* sBh = sm + 2 * ASZ;
    char* sBl = sm + 2 * ASZ + BSZ;
    const unsigned uAh = smem_u32(sAh), uAl = smem_u32(sAl);
    const unsigned uBh = smem_u32(sBh), uBl = smem_u32(sBl);

    const int tid = threadIdx.x;
    const int wid = tid >> 5;
    const int lane = tid & 31;
    const int base = blockIdx.x * 64;
    constexpr int NT = COUT / 16;            // n8-tiles per warp (8 or 4)

    // ---- A: load fp32 X tile, (ReLU), split bf16 hi/lo ----
    {
        const float4* X4 = (const float4*)X;
        #pragma unroll
        for (int i = tid; i < 64 * 32; i += 256) {
            int r = i >> 5;
            int k0 = (i & 31) * 4;
            int gr = base + r;
            float4 v = make_float4(0.f, 0.f, 0.f, 0.f);
            if (gr < NN) v = X4[gr * 32 + (k0 >> 2)];
            if (RELU) {
                v.x = fmaxf(v.x, 0.f); v.y = fmaxf(v.y, 0.f);
                v.z = fmaxf(v.z, 0.f); v.w = fmaxf(v.w, 0.f);
            }
            float rx, ry, rz, rw;
            unsigned h01 = pack_hi(v.x, v.y, rx, ry);
            unsigned h23 = pack_hi(v.z, v.w, rz, rw);
            unsigned off = (unsigned)(r * SA + k0) * 2;
            *(uint2*)(sAh + off) = make_uint2(h01, h23);
            *(uint2*)(sAl + off) = make_uint2(pack2(rx, ry), pack2(rz, rw));
        }
    }
    // ---- B: copy W^T splits (bf16 [n][128]) into padded smem ----
    {
        #pragma unroll
        for (int i = tid; i < COUT * 32; i += 256) {
            int n = i >> 5;
            int k0 = (i & 31) * 4;
            unsigned soff = (unsigned)(n * SA + k0) * 2;
            unsigned goff = (unsigned)(n * 128 + k0) * 2;
            *(uint2*)(sBh + soff) = *(const uint2*)((const char*)g_Wh + goff);
            *(uint2*)(sBl + soff) = *(const uint2*)((const char*)g_Wl + goff);
        }
    }
    __syncthreads();

    const int wr = wid & 3;
    const int wc = wid >> 2;
    const int m0 = wr * 16;
    const int n0 = wc * (COUT / 2);

    float acc[NT][4];
    #pragma unroll
    for (int j = 0; j < NT; j++)
        #pragma unroll
        for (int q = 0; q < 4; q++) acc[j][q] = 0.f;

    // intra-warp ldmatrix lane offsets
    const unsigned aoff = (unsigned)((m0 + (lane & 15)) * SA + (lane >> 4) * 8) * 2;
    const int bmat = lane >> 3;              // 0..3
    const int brow = lane & 7;
    const unsigned boff_row = (unsigned)((n0 + (bmat >> 1) * 8 + brow) * SA + (bmat & 1) * 8) * 2;

    #pragma unroll
    for (int ks = 0; ks < 8; ks++) {
        const unsigned k2 = (unsigned)(ks * 16) * 2;
        unsigned ah[4], al[4];
        ldsm4(ah, uAh + aoff + k2);
        ldsm4(al, uAl + aoff + k2);

        unsigned bh[NT][2], bl[NT][2];
        #pragma unroll
        for (int jj = 0; jj < NT / 2; jj++) {
            unsigned bo = boff_row + (unsigned)(jj * 16 * SA) * 2 + k2;
            unsigned t4[4];
            ldsm4(t4, uBh + bo);
            bh[jj * 2][0] = t4[0]; bh[jj * 2][1] = t4[1];
            bh[jj * 2 + 1][0] = t4[2]; bh[jj * 2 + 1][1] = t4[3];
            ldsm4(t4, uBl + bo);
            bl[jj * 2][0] = t4[0]; bl[jj * 2][1] = t4[1];
            bl[jj * 2 + 1][0] = t4[2]; bl[jj * 2 + 1][1] = t4[3];
        }
        #pragma unroll
        for (int j = 0; j < NT; j++) {
            mma16816(acc[j], ah, bh[j]);
            mma16816(acc[j], ah, bl[j]);
            mma16816(acc[j], al, bh[j]);
        }
    }

    // ---- epilogue: msg = fp16(h*dis) ; AGG = h/deg + b ----
    {
        const int r1 = m0 + (lane >> 2);
        const int r2 = r1 + 8;
        const int gr1 = base + r1;
        const int gr2 = base + r2;
        float ds1 = 0.f, di1 = 0.f, ds2 = 0.f, di2 = 0.f;
        if (gr1 < NN) { ds1 = g_dis[gr1]; di1 = g_deg[gr1]; }
        if (gr2 < NN) { ds2 = g_dis[gr2]; di2 = g_deg[gr2]; }
        #pragma unroll
        for (int j = 0; j < NT; j++) {
            const int col = n0 + j * 8 + (lane & 3) * 2;
            const float2 bv = *(const float2*)(bias + col);
            if (gr1 < NN) {
                *(__half2*)(Hs + gr1 * COUT + col) =
                    __floats2half2_rn(acc[j][0] * ds1, acc[j][1] * ds1);
                float2 ag = make_float2(acc[j][0] * di1 + bv.x, acc[j][1] * di1 + bv.y);
                *(float2*)(AGG + gr1 * COUT + col) = ag;
            }
            if (gr2 < NN) {
                *(__half2*)(Hs + gr2 * COUT + col) =
                    __floats2half2_rn(acc[j][2] * ds2, acc[j][3] * ds2);
                float2 ag = make_float2(acc[j][2] * di2 + bv.x, acc[j][3] * di2 + bv.y);
                *(float2*)(AGG + gr2 * COUT + col) = ag;
            }
        }
    }
}

// ======= gather aggregation (fp16 msgs): AGG[d] += dis[d]*sum msg[src] =====
template <int COUT>
__global__ __launch_bounds__(256) void k_agg(const __half* __restrict__ Hs,
                                             float* __restrict__ AGG)
{
    constexpr int LPN = COUT / 8;        // uint4 lanes per node (16 or 8)
    constexpr int NPB = 256 / LPN;       // nodes per block (16 or 32)
    int n = blockIdx.x * NPB + threadIdx.x / LPN;
    int lane = threadIdx.x % LPN;
    if (n >= NN) return;

    int beg = g_off[n];
    int end = g_off[n + 1];
    float2 a0 = make_float2(0.f, 0.f), a1 = a0, a2 = a0, a3 = a0;
    const uint4* H4 = (const uint4*)Hs;

    #define ADDV(v) do { \
        float2 f0 = __half22float2(*(const __half2*)&(v).x); \
        float2 f1 = __half22float2(*(const __half2*)&(v).y); \
        float2 f2 = __half22float2(*(const __half2*)&(v).z); \
        float2 f3 = __half22float2(*(const __half2*)&(v).w); \
        a0.x += f0.x; a0.y += f0.y; a1.x += f1.x; a1.y += f1.y; \
        a2.x += f2.x; a2.y += f2.y; a3.x += f3.x; a3.y += f3.y; \
    } while (0)

    int e = beg;
    for (; e + 3 < end; e += 4) {
        int s0 = g_csrc[e];
        int s1 = g_csrc[e + 1];
        int s2 = g_csrc[e + 2];
        int s3 = g_csrc[e + 3];
        uint4 v0 = H4[s0 * LPN + lane];
        uint4 v1 = H4[s1 * LPN + lane];
        uint4 v2 = H4[s2 * LPN + lane];
        uint4 v3 = H4[s3 * LPN + lane];
        ADDV(v0); ADDV(v1); ADDV(v2); ADDV(v3);
    }
    for (; e < end; e++) {
        uint4 v = H4[g_csrc[e] * LPN + lane];
        ADDV(v);
    }
    #undef ADDV

    float ds = g_dis[n];
    float4* row = (float4*)(AGG + n * COUT + lane * 8);
    float4 o0 = row[0];
    float4 o1 = row[1];
    o0.x += ds * a0.x; o0.y += ds * a0.y; o0.z += ds * a1.x; o0.w += ds * a1.y;
    o1.x += ds * a2.x; o1.y += ds * a2.y; o1.z += ds * a3.x; o1.w += ds * a3.y;
    row[0] = o0;
    row[1] = o1;
}

// ================= pair dot decode =================
__global__ __launch_bounds__(256) void k_pairs(
    const float* __restrict__ H,
    const void* __restrict__ ni, const void* __restrict__ nj,
    float* __restrict__ out)
{
    int t = blockIdx.x * 256 + threadIdx.x;
    int p = t >> 5;
    int lane = t & 31;
    if (p >= NP) return;
    int i = load_idx(ni, p);
    int j = load_idx(nj, p);
    float2 a = ((const float2*)H)[i * 32 + lane];
    float2 b = ((const float2*)H)[j * 32 + lane];
    float s = a.x * b.x + a.y * b.y;
    #pragma unroll
    for (int o = 16; o; o >>= 1) s += __shfl_xor_sync(0xFFFFFFFFu, s, o);
    if (lane == 0) out[p] = s;
}

// ================= launch =================
extern "C" void kernel_launch(void* const* d_in, const int* in_sizes, int n_in,
                              void* d_out, int out_size)
{
    const float* x  = (const float*)d_in[0];
    const void*  ei = d_in[1];
    const void*  ni = d_in[2];
    const void*  nj = d_in[3];
    const float* W1 = (const float*)d_in[4];
    const float* b1 = (const float*)d_in[5];
    const float* W2 = (const float*)d_in[6];
    const float* b2 = (const float*)d_in[7];
    const float* W3 = (const float*)d_in[8];
    const float* b3 = (const float*)d_in[9];
    float* out = (float*)d_out;

    __half* msg;
    float *bufB, *bufC;
    cudaGetSymbolAddress((void**)&msg,  g_msg);
    cudaGetSymbolAddress((void**)&bufB, g_bufB);
    cudaGetSymbolAddress((void**)&bufC, g_bufC);

    const int smem128 = 2 * (64 * SA * 2) + 2 * (128 * SA * 2);  // 104448
    const int smem64  = 2 * (64 * SA * 2) + 2 * (64 * SA * 2);   //  69632
    cudaFuncSetAttribute(k_mma_gemm<128, false>, cudaFuncAttributeMaxDynamicSharedMemorySize, smem128);
    cudaFuncSetAttribute(k_mma_gemm<128, true>,  cudaFuncAttributeMaxDynamicSharedMemorySize, smem128);
    cudaFuncSetAttribute(k_mma_gemm<64,  true>,  cudaFuncAttributeMaxDynamicSharedMemorySize, smem64);

    // dtype detection + degree/CSR prep
    k_detect<<<1, 32>>>(ei);
    k_zero<<<(NN + 255) / 256, 256>>>();
    k_prep<<<(NE + 255) / 256, 256>>>(ei);
    k_finalize<<<(NN + 255) / 256, 256>>>();
    k_scan<<<1, 1024>>>();
    k_place<<<(NE + 255) / 256, 256>>>();

    const int gt = (NN + 63) / 64;   // 1563 tiles

    // layer 1
    k_convW<128><<<(128 * 32) / 256, 256>>>(W1);
    k_mma_gemm<128, false><<<gt, 256, smem128>>>(x, b1, msg, bufB);
    k_agg<128><<<(NN + 15) / 16, 256>>>(msg, bufB);
    // layer 2
    k_convW<128><<<(128 * 32) / 256, 256>>>(W2);
    k_mma_gemm<128, true><<<gt, 256, smem128>>>(bufB, b2, msg, bufC);
    k_agg<128><<<(NN + 15) / 16, 256>>>(msg, bufC);
    // layer 3 (COUT=64)
    k_convW<64><<<(64 * 32) / 256, 256>>>(W3);
    k_mma_gemm<64, true><<<gt, 256, smem64>>>(bufC, b3, msg, bufB);
    k_agg<64><<<(NN + 31) / 32, 256>>>(msg, bufB);

    // link decode
    k_pairs<<<(NP * 32) / 256, 256>>>(bufB, ni, nj, out);
}